// round 1
// baseline (speedup 1.0000x reference)
#include <cuda_runtime.h>
#include <math.h>

#define N_NODES 50000
#define N_EDGES 800000
#define D 128
#define D4 32          // D/4
#define D_RED 32

// ---------------- scratch (static __device__ — no allocs allowed) ----------------
__device__ float g_bufA[N_NODES * D];
__device__ float g_bufB[N_NODES * D];
__device__ float g_feats[3][N_NODES * D];
__device__ int   g_counts[N_NODES];
__device__ int   g_rowptr[N_NODES + 1];
__device__ int   g_cursor[N_NODES];
__device__ int   g_ecol[N_EDGES];
__device__ float g_eval[N_EDGES];
__device__ float g_msum[3 * D];
__device__ float g_attn[3 * D];

__device__ __forceinline__ float* sel_buf(int s) {
    switch (s) {
        case 0: return g_bufA;
        case 1: return g_bufB;
        default: return g_feats[s - 2];
    }
}

// ---------------- CSR build ----------------
__global__ void zero_kernel() {
    int i = blockIdx.x * blockDim.x + threadIdx.x;
    if (i < N_NODES) g_counts[i] = 0;
    if (i < 3 * D)   g_msum[i] = 0.f;
}

__global__ void count_kernel(const int* __restrict__ erow) {
    int i = blockIdx.x * blockDim.x + threadIdx.x;
    if (i < N_EDGES) atomicAdd(&g_counts[erow[i]], 1);
}

__global__ void scan_kernel() {
    __shared__ int sd[1024];
    __shared__ int s_carry;
    int t = threadIdx.x;
    if (t == 0) s_carry = 0;
    __syncthreads();
    for (int base = 0; base < N_NODES; base += 1024) {
        int v = (base + t < N_NODES) ? g_counts[base + t] : 0;
        sd[t] = v;
        __syncthreads();
        for (int off = 1; off < 1024; off <<= 1) {
            int x = (t >= off) ? sd[t - off] : 0;
            __syncthreads();
            sd[t] += x;
            __syncthreads();
        }
        int excl = sd[t] - v + s_carry;
        if (base + t < N_NODES) { g_rowptr[base + t] = excl; g_cursor[base + t] = excl; }
        __syncthreads();
        if (t == 1023) s_carry += sd[1023];
        __syncthreads();
    }
    if (t == 0) g_rowptr[N_NODES] = s_carry;
}

__global__ void fill_kernel(const int* __restrict__ erow, const int* __restrict__ ecol,
                            const float* __restrict__ eval_) {
    int i = blockIdx.x * blockDim.x + threadIdx.x;
    if (i < N_EDGES) {
        int p = atomicAdd(&g_cursor[erow[i]], 1);
        g_ecol[p] = ecol[i];
        g_eval[p] = eval_[i];
    }
}

// ---------------- fused tanh(X @ W) ----------------
// block = 256 threads = 8 warps; block tile = 32 rows x 128 cols; warp = 4 rows.
// W staged in smem in two 64-row phases (32KB). X rows register-resident (float4/lane).
__global__ void gemm_tanh_kernel(const float* __restrict__ X, const float* __restrict__ W,
                                 int dst_sel) {
    __shared__ float ws[64 * D];  // 32 KB
    float* out = sel_buf(dst_sel);
    int tid = threadIdx.x;
    int warp = tid >> 5, lane = tid & 31;
    int row0 = blockIdx.x * 32 + warp * 4;

    const float4* X4 = (const float4*)X;
    float4 xr[4];
#pragma unroll
    for (int i = 0; i < 4; ++i) {
        int r = row0 + i;
        int rc = r < N_NODES ? r : N_NODES - 1;
        xr[i] = X4[rc * D4 + lane];
    }

    float acc[4][4];
#pragma unroll
    for (int i = 0; i < 4; ++i)
#pragma unroll
        for (int j = 0; j < 4; ++j) acc[i][j] = 0.f;

    const float4* W4s = (const float4*)ws;
    for (int phase = 0; phase < 2; ++phase) {
        __syncthreads();
        const float4* Wg = (const float4*)(W + phase * 64 * D);
        for (int i = tid; i < 64 * D4; i += 256) ((float4*)ws)[i] = Wg[i];
        __syncthreads();
#pragma unroll
        for (int k4 = 0; k4 < 16; ++k4) {
            int src = phase * 16 + k4;
            float4 w0 = W4s[(4 * k4 + 0) * D4 + lane];
            float4 w1 = W4s[(4 * k4 + 1) * D4 + lane];
            float4 w2 = W4s[(4 * k4 + 2) * D4 + lane];
            float4 w3 = W4s[(4 * k4 + 3) * D4 + lane];
#pragma unroll
            for (int i = 0; i < 4; ++i) {
                float a0 = __shfl_sync(0xffffffffu, xr[i].x, src);
                float a1 = __shfl_sync(0xffffffffu, xr[i].y, src);
                float a2 = __shfl_sync(0xffffffffu, xr[i].z, src);
                float a3 = __shfl_sync(0xffffffffu, xr[i].w, src);
                acc[i][0] = fmaf(a0, w0.x, fmaf(a1, w1.x, fmaf(a2, w2.x, fmaf(a3, w3.x, acc[i][0]))));
                acc[i][1] = fmaf(a0, w0.y, fmaf(a1, w1.y, fmaf(a2, w2.y, fmaf(a3, w3.y, acc[i][1]))));
                acc[i][2] = fmaf(a0, w0.z, fmaf(a1, w1.z, fmaf(a2, w2.z, fmaf(a3, w3.z, acc[i][2]))));
                acc[i][3] = fmaf(a0, w0.w, fmaf(a1, w1.w, fmaf(a2, w2.w, fmaf(a3, w3.w, acc[i][3]))));
            }
        }
    }

    float4* O4 = (float4*)out;
#pragma unroll
    for (int i = 0; i < 4; ++i) {
        int r = row0 + i;
        if (r < N_NODES) {
            float4 o;
            o.x = tanhf(acc[i][0]);
            o.y = tanhf(acc[i][1]);
            o.z = tanhf(acc[i][2]);
            o.w = tanhf(acc[i][3]);
            O4[r * D4 + lane] = o;
        }
    }
}

// ---------------- SpMM: warp-per-row, CSR, float4 gather, 4-edge unroll ----------------
__global__ void spmm_kernel(int src_sel, int dst_sel, const float* __restrict__ bias) {
    const float* xin = sel_buf(src_sel);
    float* out = sel_buf(dst_sel);
    int warp = threadIdx.x >> 5, lane = threadIdx.x & 31;
    int row = blockIdx.x * (blockDim.x >> 5) + warp;
    if (row >= N_NODES) return;
    int s = g_rowptr[row], e = g_rowptr[row + 1];
    const float4* x4 = (const float4*)xin;
    float4 acc = make_float4(0.f, 0.f, 0.f, 0.f);

    for (int b = s; b < e; b += 32) {
        int idx = b + lane;
        int c = 0;
        float v = 0.f;
        if (idx < e) { c = g_ecol[idx]; v = g_eval[idx]; }
        int cnt = min(32, e - b);
        int j = 0;
        for (; j + 4 <= cnt; j += 4) {
            int c0 = __shfl_sync(0xffffffffu, c, j + 0);
            int c1 = __shfl_sync(0xffffffffu, c, j + 1);
            int c2 = __shfl_sync(0xffffffffu, c, j + 2);
            int c3 = __shfl_sync(0xffffffffu, c, j + 3);
            float v0 = __shfl_sync(0xffffffffu, v, j + 0);
            float v1 = __shfl_sync(0xffffffffu, v, j + 1);
            float v2 = __shfl_sync(0xffffffffu, v, j + 2);
            float v3 = __shfl_sync(0xffffffffu, v, j + 3);
            float4 x0 = x4[c0 * D4 + lane];
            float4 x1 = x4[c1 * D4 + lane];
            float4 x2 = x4[c2 * D4 + lane];
            float4 x3 = x4[c3 * D4 + lane];
            acc.x = fmaf(v0, x0.x, fmaf(v1, x1.x, fmaf(v2, x2.x, fmaf(v3, x3.x, acc.x))));
            acc.y = fmaf(v0, x0.y, fmaf(v1, x1.y, fmaf(v2, x2.y, fmaf(v3, x3.y, acc.y))));
            acc.z = fmaf(v0, x0.z, fmaf(v1, x1.z, fmaf(v2, x2.z, fmaf(v3, x3.z, acc.z))));
            acc.w = fmaf(v0, x0.w, fmaf(v1, x1.w, fmaf(v2, x2.w, fmaf(v3, x3.w, acc.w))));
        }
        for (; j < cnt; ++j) {
            int cc = __shfl_sync(0xffffffffu, c, j);
            float vv = __shfl_sync(0xffffffffu, v, j);
            float4 xv = x4[cc * D4 + lane];
            acc.x = fmaf(vv, xv.x, acc.x);
            acc.y = fmaf(vv, xv.y, acc.y);
            acc.z = fmaf(vv, xv.z, acc.z);
            acc.w = fmaf(vv, xv.w, acc.w);
        }
    }
    if (bias) {
        float4 bb = ((const float4*)bias)[lane];
        acc.x += bb.x; acc.y += bb.y; acc.z += bb.z; acc.w += bb.w;
    }
    ((float4*)out)[row * D4 + lane] = acc;
}

// ---------------- mean over nodes (block-partial + atomic) ----------------
__global__ void mean_kernel() {
    int br = blockIdx.y;
    int d = threadIdx.x;  // 128
    int r0 = blockIdx.x * 256;
    int rend = min(r0 + 256, N_NODES);
    const float* f = g_feats[br];
    float s = 0.f;
    for (int r = r0; r < rend; ++r) s += f[r * D + d];
    atomicAdd(&g_msum[br * D + d], s);
}

// ---------------- tiny MLP + softmax over order ----------------
__global__ void mlp_kernel(const float* __restrict__ fc1w, const float* __restrict__ fc1b,
                           const float* __restrict__ fc2w, const float* __restrict__ fc2b) {
    __shared__ float m[3 * D];
    __shared__ float t1[3 * D_RED];
    int t = threadIdx.x;  // 128
    for (int i = t; i < 3 * D; i += 128) m[i] = g_msum[i] * (1.0f / N_NODES);
    __syncthreads();
    if (t < 3 * D_RED) {
        int k = t / D_RED, r = t % D_RED;
        float s = fc1b[r];
        for (int d = 0; d < D; ++d) s = fmaf(m[k * D + d], fc1w[d * D_RED + r], s);
        t1[t] = s > 0.f ? s : 0.f;
    }
    __syncthreads();
    float lg[3];
#pragma unroll
    for (int k = 0; k < 3; ++k) {
        float s = fc2b[t];
        for (int r = 0; r < D_RED; ++r) s = fmaf(t1[k * D_RED + r], fc2w[r * D + t], s);
        lg[k] = s;
    }
    float mx = fmaxf(lg[0], fmaxf(lg[1], lg[2]));
    float e0 = expf(lg[0] - mx), e1 = expf(lg[1] - mx), e2 = expf(lg[2] - mx);
    float inv = 1.f / (e0 + e1 + e2);
    g_attn[0 * D + t] = e0 * inv;
    g_attn[1 * D + t] = e1 * inv;
    g_attn[2 * D + t] = e2 * inv;
}

// ---------------- weighted combine ----------------
__global__ void combine_kernel(float* __restrict__ out) {
    __shared__ float4 sa[3 * D4];
    if (threadIdx.x < 3 * D4) sa[threadIdx.x] = ((const float4*)g_attn)[threadIdx.x];
    __syncthreads();
    int i = blockIdx.x * blockDim.x + threadIdx.x;  // over N*D4 float4s (exact)
    int q = i & (D4 - 1);
    float4 f0 = ((const float4*)g_feats[0])[i];
    float4 f1 = ((const float4*)g_feats[1])[i];
    float4 f2 = ((const float4*)g_feats[2])[i];
    float4 a0 = sa[q], a1 = sa[D4 + q], a2 = sa[2 * D4 + q];
    float4 o;
    o.x = f0.x * a0.x + f1.x * a1.x + f2.x * a2.x;
    o.y = f0.y * a0.y + f1.y * a1.y + f2.y * a2.y;
    o.z = f0.z * a0.z + f1.z * a1.z + f2.z * a2.z;
    o.w = f0.w * a0.w + f1.w * a1.w + f2.w * a2.w;
    ((float4*)out)[i] = o;
}

// ---------------- launch ----------------
extern "C" void kernel_launch(void* const* d_in, const int* in_sizes, int n_in,
                              void* d_out, int out_size) {
    const float* features = (const float*)d_in[0];
    const int*   erow     = (const int*)d_in[1];
    const int*   ecol     = (const int*)d_in[2];
    const float* eval_    = (const float*)d_in[3];
    const float* Ws[3]    = {(const float*)d_in[4], (const float*)d_in[6], (const float*)d_in[8]};
    const float* Bs[3]    = {(const float*)d_in[5], (const float*)d_in[7], (const float*)d_in[9]};
    const float* fc1w     = (const float*)d_in[10];
    const float* fc1b     = (const float*)d_in[11];
    const float* fc2w     = (const float*)d_in[12];
    const float* fc2b     = (const float*)d_in[13];
    float* out = (float*)d_out;

    // CSR build
    zero_kernel<<<(N_NODES + 255) / 256, 256>>>();
    count_kernel<<<(N_EDGES + 255) / 256, 256>>>(erow);
    scan_kernel<<<1, 1024>>>();
    fill_kernel<<<(N_EDGES + 255) / 256, 256>>>(erow, ecol, eval_);

    const int gemm_grid = (N_NODES + 31) / 32;
    const int spmm_grid = (N_NODES + 7) / 8;

    // branch 0: 1 hop
    gemm_tanh_kernel<<<gemm_grid, 256>>>(features, Ws[0], 0);
    spmm_kernel<<<spmm_grid, 256>>>(0, 2, Bs[0]);
    // branch 1: 2 hops
    gemm_tanh_kernel<<<gemm_grid, 256>>>(features, Ws[1], 0);
    spmm_kernel<<<spmm_grid, 256>>>(0, 1, nullptr);
    spmm_kernel<<<spmm_grid, 256>>>(1, 3, Bs[1]);
    // branch 2: 3 hops
    gemm_tanh_kernel<<<gemm_grid, 256>>>(features, Ws[2], 0);
    spmm_kernel<<<spmm_grid, 256>>>(0, 1, nullptr);
    spmm_kernel<<<spmm_grid, 256>>>(1, 0, nullptr);
    spmm_kernel<<<spmm_grid, 256>>>(0, 4, Bs[2]);

    // attention + combine
    dim3 mg((N_NODES + 255) / 256, 3);
    mean_kernel<<<mg, 128>>>();
    mlp_kernel<<<1, 128>>>(fc1w, fc1b, fc2w, fc2b);
    combine_kernel<<<(N_NODES * D4) / 256, 256>>>(out);
}

// round 2
// speedup vs baseline: 1.2646x; 1.2646x over previous
#include <cuda_runtime.h>
#include <cuda_fp16.h>
#include <mma.h>
#include <math.h>

using namespace nvcuda;

#define N_NODES 50000
#define N_PAD   50048      // padded to 64-row multiple for wmma tiles
#define N_EDGES 800000
#define D 128
#define D4 32              // D/4
#define D_RED 32

// ---------------- scratch (static __device__ — no allocs allowed) ----------------
__device__ __half g_h[3][N_PAD * D];        // tanh(X@Wk) in fp16
__device__ __half g_t2[N_NODES * D];        // A h2
__device__ __half g_t3[N_NODES * D];        // A h3
__device__ __half g_u3[N_NODES * D];        // A^2 h3
__device__ float  g_feats[3][N_NODES * D];  // branch outputs (fp32)
__device__ int    g_counts[N_NODES];
__device__ int    g_rowptr[N_NODES + 1];
__device__ int    g_cursor[N_NODES];
__device__ int    g_ecol[N_EDGES];
__device__ float  g_eval[N_EDGES];
__device__ float  g_msum[3 * D];
__device__ float  g_attn[3 * D];

// ---------------- CSR build ----------------
__global__ void zero_kernel() {
    int i = blockIdx.x * blockDim.x + threadIdx.x;
    if (i < N_NODES) g_counts[i] = 0;
    if (i < 3 * D)   g_msum[i] = 0.f;
}

__global__ void count_kernel(const int* __restrict__ erow) {
    int stride = blockDim.x * gridDim.x;
    for (int i = blockIdx.x * blockDim.x + threadIdx.x; i < N_EDGES; i += stride)
        atomicAdd(&g_counts[erow[i]], 1);
}

// single-block warp-shuffle scan: each thread owns 49 consecutive counts
__global__ void scan_kernel() {
    const int PER = 49;  // 1024*49 = 50176 >= N_NODES
    int t = threadIdx.x;
    int base = t * PER;
    int sum = 0;
    for (int i = 0; i < PER; ++i) {
        int idx = base + i;
        if (idx < N_NODES) sum += g_counts[idx];
    }
    int lane = t & 31, wid = t >> 5;
    int x = sum;
#pragma unroll
    for (int o = 1; o < 32; o <<= 1) {
        int y = __shfl_up_sync(0xffffffffu, x, o);
        if (lane >= o) x += y;
    }
    __shared__ int wsum[32];
    if (lane == 31) wsum[wid] = x;
    __syncthreads();
    if (wid == 0) {
        int w = wsum[lane];
#pragma unroll
        for (int o = 1; o < 32; o <<= 1) {
            int y = __shfl_up_sync(0xffffffffu, w, o);
            if (lane >= o) w += y;
        }
        wsum[lane] = w;
    }
    __syncthreads();
    int excl = x - sum + (wid > 0 ? wsum[wid - 1] : 0);
    int run = excl;
    for (int i = 0; i < PER; ++i) {
        int idx = base + i;
        if (idx < N_NODES) {
            g_rowptr[idx] = run;
            g_cursor[idx] = run;
            run += g_counts[idx];
        }
    }
    if (t == 1023) g_rowptr[N_NODES] = run;
}

__global__ void fill_kernel(const int* __restrict__ erow, const int* __restrict__ ecol,
                            const float* __restrict__ eval_) {
    int stride = blockDim.x * gridDim.x;
    for (int i = blockIdx.x * blockDim.x + threadIdx.x; i < N_EDGES; i += stride) {
        int p = atomicAdd(&g_cursor[erow[i]], 1);
        g_ecol[p] = ecol[i];
        g_eval[p] = eval_[i];
    }
}

// ---------------- tanh(X @ W) via wmma, fp16 out ----------------
// block 256 = 8 warps; block tile 64 rows x 128 cols; warp tile 16 x 64.
__global__ __launch_bounds__(256) void gemm_tanh_wmma(const float* __restrict__ X,
                                                      const float* __restrict__ Wg,
                                                      int ksel) {
    __shared__ __half As[64 * D];   // 16 KB
    __shared__ __half Bs[D * D];    // 32 KB
    __half* out = g_h[ksel];
    int tid = threadIdx.x;
    int row0 = blockIdx.x * 64;

    for (int i = tid; i < D * D; i += 256) Bs[i] = __float2half(Wg[i]);
    for (int i = tid; i < 64 * D; i += 256) {
        int j = i >> 7, col = i & 127;
        int r = row0 + j;
        if (r >= N_NODES) r = N_NODES - 1;
        As[i] = __float2half(X[r * D + col]);
    }
    __syncthreads();

    int warp = tid >> 5;
    int wr = warp >> 1;             // 0..3 row tile
    int wc0 = (warp & 1) * 4;       // col tile base (x16)

    wmma::fragment<wmma::accumulator, 16, 16, 16, float> acc[4];
#pragma unroll
    for (int c = 0; c < 4; ++c) wmma::fill_fragment(acc[c], 0.f);

#pragma unroll
    for (int k16 = 0; k16 < 8; ++k16) {
        wmma::fragment<wmma::matrix_a, 16, 16, 16, __half, wmma::row_major> a;
        wmma::load_matrix_sync(a, As + wr * 16 * D + k16 * 16, D);
#pragma unroll
        for (int c = 0; c < 4; ++c) {
            wmma::fragment<wmma::matrix_b, 16, 16, 16, __half, wmma::row_major> b;
            wmma::load_matrix_sync(b, Bs + k16 * 16 * D + (wc0 + c) * 16, D);
            wmma::mma_sync(acc[c], a, b, acc[c]);
        }
    }
#pragma unroll
    for (int c = 0; c < 4; ++c) {
        wmma::fragment<wmma::accumulator, 16, 16, 16, __half> hacc;
#pragma unroll
        for (int i = 0; i < hacc.num_elements; ++i)
            hacc.x[i] = __float2half(tanhf(acc[c].x[i]));
        wmma::store_matrix_sync(out + (row0 + wr * 16) * D + (wc0 + c) * 16, hacc, D,
                                wmma::mem_row_major);
    }
}

// ---------------- fused multi-branch SpMM hop ----------------
__device__ __forceinline__ void fma4h(float4& a, float v, uint2 p) {
    float2 f0 = __half22float2(*reinterpret_cast<const __half2*>(&p.x));
    float2 f1 = __half22float2(*reinterpret_cast<const __half2*>(&p.y));
    a.x = fmaf(v, f0.x, a.x);
    a.y = fmaf(v, f0.y, a.y);
    a.z = fmaf(v, f1.x, a.z);
    a.w = fmaf(v, f1.y, a.w);
}

__device__ __forceinline__ uint2 pack4h(float4 a) {
    __half2 l = __floats2half2_rn(a.x, a.y);
    __half2 h = __floats2half2_rn(a.z, a.w);
    uint2 r;
    r.x = *reinterpret_cast<unsigned*>(&l);
    r.y = *reinterpret_cast<unsigned*>(&h);
    return r;
}

// M = number of live branch streams this hop. Stream 0 finishes: fp32 out + bias.
// Streams 1..M-1 continue: fp16 out.
template <int M>
__global__ __launch_bounds__(256) void hop_kernel(const float* __restrict__ bias) {
    const uint2 *in0, *in1 = nullptr, *in2 = nullptr;
    float* fout;
    uint2 *o1 = nullptr, *o2 = nullptr;
    if constexpr (M == 3) {
        in0 = (const uint2*)g_h[0]; in1 = (const uint2*)g_h[1]; in2 = (const uint2*)g_h[2];
        fout = g_feats[0]; o1 = (uint2*)g_t2; o2 = (uint2*)g_t3;
    } else if constexpr (M == 2) {
        in0 = (const uint2*)g_t2; in1 = (const uint2*)g_t3;
        fout = g_feats[1]; o1 = (uint2*)g_u3;
    } else {
        in0 = (const uint2*)g_u3;
        fout = g_feats[2];
    }

    int warp = threadIdx.x >> 5, lane = threadIdx.x & 31;
    int row = blockIdx.x * 8 + warp;
    if (row >= N_NODES) return;
    int s = g_rowptr[row], e = g_rowptr[row + 1];

    float4 a0 = make_float4(0.f, 0.f, 0.f, 0.f), a1 = a0, a2 = a0;

    for (int b = s; b < e; b += 32) {
        int idx = b + lane;
        int c = 0;
        float v = 0.f;
        if (idx < e) { c = __ldg(&g_ecol[idx]); v = __ldg(&g_eval[idx]); }
        int cnt = min(32, e - b);
        int j = 0;
        for (; j + 2 <= cnt; j += 2) {
            int c0 = __shfl_sync(0xffffffffu, c, j);
            int c1 = __shfl_sync(0xffffffffu, c, j + 1);
            float v0 = __shfl_sync(0xffffffffu, v, j);
            float v1 = __shfl_sync(0xffffffffu, v, j + 1);
            int off0 = c0 * D4 + lane, off1 = c1 * D4 + lane;
            uint2 q00 = in0[off0], q01 = in0[off1];
            uint2 q10, q11, q20, q21;
            if (M > 1) { q10 = in1[off0]; q11 = in1[off1]; }
            if (M > 2) { q20 = in2[off0]; q21 = in2[off1]; }
            fma4h(a0, v0, q00); fma4h(a0, v1, q01);
            if (M > 1) { fma4h(a1, v0, q10); fma4h(a1, v1, q11); }
            if (M > 2) { fma4h(a2, v0, q20); fma4h(a2, v1, q21); }
        }
        if (j < cnt) {
            int c0 = __shfl_sync(0xffffffffu, c, j);
            float v0 = __shfl_sync(0xffffffffu, v, j);
            int off0 = c0 * D4 + lane;
            fma4h(a0, v0, in0[off0]);
            if (M > 1) fma4h(a1, v0, in1[off0]);
            if (M > 2) fma4h(a2, v0, in2[off0]);
        }
    }

    float4 bb = ((const float4*)bias)[lane];
    a0.x += bb.x; a0.y += bb.y; a0.z += bb.z; a0.w += bb.w;
    ((float4*)fout)[row * D4 + lane] = a0;
    if (M > 1) o1[row * D4 + lane] = pack4h(a1);
    if (M > 2) o2[row * D4 + lane] = pack4h(a2);
}

// ---------------- mean over nodes ----------------
__global__ void mean_kernel() {
    int br = blockIdx.y;
    int d = threadIdx.x;  // 128
    int r0 = blockIdx.x * 256;
    int rend = min(r0 + 256, N_NODES);
    const float* f = g_feats[br];
    float s = 0.f;
    for (int r = r0; r < rend; ++r) s += f[r * D + d];
    atomicAdd(&g_msum[br * D + d], s);
}

// ---------------- tiny MLP + softmax over order ----------------
__global__ void mlp_kernel(const float* __restrict__ fc1w, const float* __restrict__ fc1b,
                           const float* __restrict__ fc2w, const float* __restrict__ fc2b) {
    __shared__ float m[3 * D];
    __shared__ float t1[3 * D_RED];
    int t = threadIdx.x;  // 128
    for (int i = t; i < 3 * D; i += 128) m[i] = g_msum[i] * (1.0f / N_NODES);
    __syncthreads();
    if (t < 3 * D_RED) {
        int k = t / D_RED, r = t % D_RED;
        float s = fc1b[r];
        for (int d = 0; d < D; ++d) s = fmaf(m[k * D + d], fc1w[d * D_RED + r], s);
        t1[t] = s > 0.f ? s : 0.f;
    }
    __syncthreads();
    float lg[3];
#pragma unroll
    for (int k = 0; k < 3; ++k) {
        float s = fc2b[t];
        for (int r = 0; r < D_RED; ++r) s = fmaf(t1[k * D_RED + r], fc2w[r * D + t], s);
        lg[k] = s;
    }
    float mx = fmaxf(lg[0], fmaxf(lg[1], lg[2]));
    float e0 = expf(lg[0] - mx), e1 = expf(lg[1] - mx), e2 = expf(lg[2] - mx);
    float inv = 1.f / (e0 + e1 + e2);
    g_attn[0 * D + t] = e0 * inv;
    g_attn[1 * D + t] = e1 * inv;
    g_attn[2 * D + t] = e2 * inv;
}

// ---------------- weighted combine ----------------
__global__ void combine_kernel(float* __restrict__ out) {
    __shared__ float4 sa[3 * D4];
    if (threadIdx.x < 3 * D4) sa[threadIdx.x] = ((const float4*)g_attn)[threadIdx.x];
    __syncthreads();
    int i = blockIdx.x * blockDim.x + threadIdx.x;  // over N*D4 float4s (exact)
    int q = i & (D4 - 1);
    float4 f0 = ((const float4*)g_feats[0])[i];
    float4 f1 = ((const float4*)g_feats[1])[i];
    float4 f2 = ((const float4*)g_feats[2])[i];
    float4 a0 = sa[q], a1 = sa[D4 + q], a2 = sa[2 * D4 + q];
    float4 o;
    o.x = f0.x * a0.x + f1.x * a1.x + f2.x * a2.x;
    o.y = f0.y * a0.y + f1.y * a1.y + f2.y * a2.y;
    o.z = f0.z * a0.z + f1.z * a1.z + f2.z * a2.z;
    o.w = f0.w * a0.w + f1.w * a1.w + f2.w * a2.w;
    ((float4*)out)[i] = o;
}

// ---------------- launch ----------------
extern "C" void kernel_launch(void* const* d_in, const int* in_sizes, int n_in,
                              void* d_out, int out_size) {
    const float* features = (const float*)d_in[0];
    const int*   erow     = (const int*)d_in[1];
    const int*   ecol     = (const int*)d_in[2];
    const float* eval_    = (const float*)d_in[3];
    const float* W1 = (const float*)d_in[4];
    const float* B1 = (const float*)d_in[5];
    const float* W2 = (const float*)d_in[6];
    const float* B2 = (const float*)d_in[7];
    const float* W3 = (const float*)d_in[8];
    const float* B3 = (const float*)d_in[9];
    const float* fc1w = (const float*)d_in[10];
    const float* fc1b = (const float*)d_in[11];
    const float* fc2w = (const float*)d_in[12];
    const float* fc2b = (const float*)d_in[13];
    float* out = (float*)d_out;

    // CSR build
    zero_kernel<<<196, 256>>>();
    count_kernel<<<400, 256>>>(erow);
    scan_kernel<<<1, 1024>>>();
    fill_kernel<<<400, 256>>>(erow, ecol, eval_);

    // tanh GEMMs (tensor cores, fp16 out)
    gemm_tanh_wmma<<<N_PAD / 64, 256>>>(features, W1, 0);
    gemm_tanh_wmma<<<N_PAD / 64, 256>>>(features, W2, 1);
    gemm_tanh_wmma<<<N_PAD / 64, 256>>>(features, W3, 2);

    // fused hops: A (3 streams), B (2), C (1)
    const int hop_grid = (N_NODES + 7) / 8;
    hop_kernel<3><<<hop_grid, 256>>>(B1);
    hop_kernel<2><<<hop_grid, 256>>>(B2);
    hop_kernel<1><<<hop_grid, 256>>>(B3);

    // attention + combine
    dim3 mg((N_NODES + 255) / 256, 3);
    mean_kernel<<<mg, 128>>>();
    mlp_kernel<<<1, 128>>>(fc1w, fc1b, fc2w, fc2b);
    combine_kernel<<<(N_NODES * D4) / 256, 256>>>(out);
}

// round 3
// speedup vs baseline: 1.3081x; 1.0344x over previous
#include <cuda_runtime.h>
#include <cuda_fp16.h>
#include <mma.h>
#include <math.h>

using namespace nvcuda;

#define N_NODES 50000
#define N_PAD   50048
#define N_EDGES 800000
#define D 128
#define D_RED 32

// ---------------- scratch ----------------
__device__ __half g_x16[N_PAD * D];
__device__ __half g_h[3][N_PAD * D];
__device__ __half g_t2[N_NODES * D];
__device__ __half g_t3[N_NODES * D];
__device__ __half g_u3[N_NODES * D];
__device__ __half g_feats16[3][N_NODES * D];
__device__ int    g_counts[N_NODES];
__device__ int    g_rowptr[N_NODES + 1];
__device__ int    g_cursor[N_NODES];
__device__ uint2  g_epack[N_EDGES];     // (col, val bits)
__device__ float  g_msum[3 * D];
__device__ float  g_attn[3 * D];

// ---------------- CSR build ----------------
__global__ void zero_kernel() {
    int i = blockIdx.x * blockDim.x + threadIdx.x;
    if (i < N_NODES) g_counts[i] = 0;
    if (i < 3 * D)   g_msum[i] = 0.f;
}

__global__ void count_kernel(const int* __restrict__ erow) {
    int i = blockIdx.x * blockDim.x + threadIdx.x;
    if (i < N_EDGES / 4) {
        int4 r = ((const int4*)erow)[i];
        atomicAdd(&g_counts[r.x], 1);
        atomicAdd(&g_counts[r.y], 1);
        atomicAdd(&g_counts[r.z], 1);
        atomicAdd(&g_counts[r.w], 1);
    }
}

__global__ void scan_kernel() {
    const int PER = 49;
    int t = threadIdx.x;
    int base = t * PER;
    int sum = 0;
    for (int i = 0; i < PER; ++i) {
        int idx = base + i;
        if (idx < N_NODES) sum += g_counts[idx];
    }
    int lane = t & 31, wid = t >> 5;
    int x = sum;
#pragma unroll
    for (int o = 1; o < 32; o <<= 1) {
        int y = __shfl_up_sync(0xffffffffu, x, o);
        if (lane >= o) x += y;
    }
    __shared__ int wsum[32];
    if (lane == 31) wsum[wid] = x;
    __syncthreads();
    if (wid == 0) {
        int w = wsum[lane];
#pragma unroll
        for (int o = 1; o < 32; o <<= 1) {
            int y = __shfl_up_sync(0xffffffffu, w, o);
            if (lane >= o) w += y;
        }
        wsum[lane] = w;
    }
    __syncthreads();
    int run = x - sum + (wid > 0 ? wsum[wid - 1] : 0);
    for (int i = 0; i < PER; ++i) {
        int idx = base + i;
        if (idx < N_NODES) {
            g_rowptr[idx] = run;
            g_cursor[idx] = run;
            run += g_counts[idx];
        }
    }
    if (t == 1023) g_rowptr[N_NODES] = run;
}

__global__ void fill_kernel(const int* __restrict__ erow, const int* __restrict__ ecol,
                            const float* __restrict__ eval_) {
    int i = blockIdx.x * blockDim.x + threadIdx.x;
    if (i < N_EDGES / 4) {
        int4 r = ((const int4*)erow)[i];
        int4 c = ((const int4*)ecol)[i];
        float4 v = ((const float4*)eval_)[i];
        int p0 = atomicAdd(&g_cursor[r.x], 1);
        int p1 = atomicAdd(&g_cursor[r.y], 1);
        int p2 = atomicAdd(&g_cursor[r.z], 1);
        int p3 = atomicAdd(&g_cursor[r.w], 1);
        g_epack[p0] = make_uint2((unsigned)c.x, __float_as_uint(v.x));
        g_epack[p1] = make_uint2((unsigned)c.y, __float_as_uint(v.y));
        g_epack[p2] = make_uint2((unsigned)c.z, __float_as_uint(v.z));
        g_epack[p3] = make_uint2((unsigned)c.w, __float_as_uint(v.w));
    }
}

// ---------------- X -> fp16 (once) ----------------
__global__ void cvt_x16_kernel(const float* __restrict__ X) {
    int i = blockIdx.x * blockDim.x + threadIdx.x;   // over N_PAD*16 uint4s
    if (i >= N_PAD * 16) return;
    int r = i >> 4;
    uint4 o = make_uint4(0, 0, 0, 0);
    if (r < N_NODES) {
        const float4* x4 = (const float4*)X;
        float4 f0 = x4[i * 2], f1 = x4[i * 2 + 1];
        __half2 h0 = __floats2half2_rn(f0.x, f0.y);
        __half2 h1 = __floats2half2_rn(f0.z, f0.w);
        __half2 h2 = __floats2half2_rn(f1.x, f1.y);
        __half2 h3 = __floats2half2_rn(f1.z, f1.w);
        o.x = *(unsigned*)&h0; o.y = *(unsigned*)&h1;
        o.z = *(unsigned*)&h2; o.w = *(unsigned*)&h3;
    }
    ((uint4*)g_x16)[i] = o;
}

// ---------------- fused tanh(X @ Wk), k = blockIdx.y ----------------
__global__ __launch_bounds__(256) void gemm_tanh_wmma(const float* __restrict__ W1,
                                                      const float* __restrict__ W2,
                                                      const float* __restrict__ W3) {
    __shared__ __half As[64 * D];   // 16 KB
    __shared__ __half Bs[D * D];    // 32 KB
    int k = blockIdx.y;
    const float* Wg = (k == 0) ? W1 : (k == 1) ? W2 : W3;
    __half* out = g_h[k];
    int tid = threadIdx.x;
    int row0 = blockIdx.x * 64;

    for (int i = tid; i < D * D; i += 256) Bs[i] = __float2half(Wg[i]);
    {
        const uint4* src = (const uint4*)(g_x16 + row0 * D);
        uint4* dst = (uint4*)As;
        for (int i = tid; i < 64 * 16; i += 256) dst[i] = src[i];
    }
    __syncthreads();

    int warp = tid >> 5;
    int wr = warp >> 1;
    int wc0 = (warp & 1) * 4;

    wmma::fragment<wmma::accumulator, 16, 16, 16, float> acc[4];
#pragma unroll
    for (int c = 0; c < 4; ++c) wmma::fill_fragment(acc[c], 0.f);

#pragma unroll
    for (int k16 = 0; k16 < 8; ++k16) {
        wmma::fragment<wmma::matrix_a, 16, 16, 16, __half, wmma::row_major> a;
        wmma::load_matrix_sync(a, As + wr * 16 * D + k16 * 16, D);
#pragma unroll
        for (int c = 0; c < 4; ++c) {
            wmma::fragment<wmma::matrix_b, 16, 16, 16, __half, wmma::row_major> b;
            wmma::load_matrix_sync(b, Bs + k16 * 16 * D + (wc0 + c) * 16, D);
            wmma::mma_sync(acc[c], a, b, acc[c]);
        }
    }
#pragma unroll
    for (int c = 0; c < 4; ++c) {
        wmma::fragment<wmma::accumulator, 16, 16, 16, __half> hacc;
#pragma unroll
        for (int i = 0; i < hacc.num_elements; ++i)
            hacc.x[i] = __float2half(tanhf(acc[c].x[i]));
        wmma::store_matrix_sync(out + (row0 + wr * 16) * D + (wc0 + c) * 16, hacc, D,
                                wmma::mem_row_major);
    }
}

// ---------------- hop helpers ----------------
__device__ __forceinline__ void fma8(float* a, float v, uint4 q) {
    float2 f0 = __half22float2(*reinterpret_cast<const __half2*>(&q.x));
    float2 f1 = __half22float2(*reinterpret_cast<const __half2*>(&q.y));
    float2 f2 = __half22float2(*reinterpret_cast<const __half2*>(&q.z));
    float2 f3 = __half22float2(*reinterpret_cast<const __half2*>(&q.w));
    a[0] = fmaf(v, f0.x, a[0]); a[1] = fmaf(v, f0.y, a[1]);
    a[2] = fmaf(v, f1.x, a[2]); a[3] = fmaf(v, f1.y, a[3]);
    a[4] = fmaf(v, f2.x, a[4]); a[5] = fmaf(v, f2.y, a[5]);
    a[6] = fmaf(v, f3.x, a[6]); a[7] = fmaf(v, f3.y, a[7]);
}

__device__ __forceinline__ uint4 pack8(const float* a) {
    __half2 h0 = __floats2half2_rn(a[0], a[1]);
    __half2 h1 = __floats2half2_rn(a[2], a[3]);
    __half2 h2 = __floats2half2_rn(a[4], a[5]);
    __half2 h3 = __floats2half2_rn(a[6], a[7]);
    uint4 r;
    r.x = *(unsigned*)&h0; r.y = *(unsigned*)&h1;
    r.z = *(unsigned*)&h2; r.w = *(unsigned*)&h3;
    return r;
}

// ---------------- fused multi-branch SpMM hop ----------------
// Half-warp per row: 16 lanes x uint4 (16B) = 256B row gather. 2 rows/warp.
template <int M>
__global__ __launch_bounds__(256) void hop_kernel(const float* __restrict__ bias) {
    const uint4 *in0, *in1 = nullptr, *in2 = nullptr;
    uint4 *fout, *o1 = nullptr, *o2 = nullptr;
    if constexpr (M == 3) {
        in0 = (const uint4*)g_h[0]; in1 = (const uint4*)g_h[1]; in2 = (const uint4*)g_h[2];
        fout = (uint4*)g_feats16[0]; o1 = (uint4*)g_t2; o2 = (uint4*)g_t3;
    } else if constexpr (M == 2) {
        in0 = (const uint4*)g_t2; in1 = (const uint4*)g_t3;
        fout = (uint4*)g_feats16[1]; o1 = (uint4*)g_u3;
    } else {
        in0 = (const uint4*)g_u3;
        fout = (uint4*)g_feats16[2];
    }

    int lane = threadIdx.x & 31;
    int warp = threadIdx.x >> 5;
    int hl = lane & 15;
    int halfsel = lane & 16;
    int row = blockIdx.x * 16 + warp * 2 + (lane >> 4);
    bool valid = row < N_NODES;
    int s = valid ? g_rowptr[row] : 0;
    int e = valid ? g_rowptr[row + 1] : 0;
    int nb = (e - s + 15) >> 4;
    int nbo = __shfl_xor_sync(0xffffffffu, nb, 16);
    int nbmax = max(nb, nbo);

    float a0[8], a1[8], a2[8];
#pragma unroll
    for (int i = 0; i < 8; ++i) { a0[i] = 0.f; a1[i] = 0.f; a2[i] = 0.f; }

    const uint4 z = make_uint4(0, 0, 0, 0);

    for (int it = 0; it < nbmax; ++it) {
        int b = s + it * 16;
        int idx = b + hl;
        int c = 0;
        float v = 0.f;
        if (idx < e) {
            uint2 p = __ldg(&g_epack[idx]);
            c = (int)p.x;
            v = __uint_as_float(p.y);
        }
        int cnt = min(16, max(0, e - b));
        int cnto = __shfl_xor_sync(0xffffffffu, cnt, 16);
        int cmax = max(cnt, cnto);
        int j = 0;
        for (; j + 2 <= cmax; j += 2) {
            int s0 = halfsel | j, s1 = halfsel | (j + 1);
            int c0 = __shfl_sync(0xffffffffu, c, s0);
            float v0 = __shfl_sync(0xffffffffu, v, s0);
            int c1 = __shfl_sync(0xffffffffu, c, s1);
            float v1 = __shfl_sync(0xffffffffu, v, s1);
            bool d0 = j < cnt, d1 = (j + 1) < cnt;
            int off0 = c0 * 16 + hl, off1 = c1 * 16 + hl;
            uint4 q00 = d0 ? __ldg(&in0[off0]) : z;
            uint4 q01 = d1 ? __ldg(&in0[off1]) : z;
            uint4 q10, q11, q20, q21;
            if (M > 1) { q10 = d0 ? __ldg(&in1[off0]) : z; q11 = d1 ? __ldg(&in1[off1]) : z; }
            if (M > 2) { q20 = d0 ? __ldg(&in2[off0]) : z; q21 = d1 ? __ldg(&in2[off1]) : z; }
            fma8(a0, v0, q00); fma8(a0, v1, q01);
            if (M > 1) { fma8(a1, v0, q10); fma8(a1, v1, q11); }
            if (M > 2) { fma8(a2, v0, q20); fma8(a2, v1, q21); }
        }
        if (j < cmax) {
            int s0 = halfsel | j;
            int c0 = __shfl_sync(0xffffffffu, c, s0);
            float v0 = __shfl_sync(0xffffffffu, v, s0);
            bool d0 = j < cnt;
            int off0 = c0 * 16 + hl;
            uint4 q00 = d0 ? __ldg(&in0[off0]) : z;
            fma8(a0, v0, q00);
            if (M > 1) { uint4 q10 = d0 ? __ldg(&in1[off0]) : z; fma8(a1, v0, q10); }
            if (M > 2) { uint4 q20 = d0 ? __ldg(&in2[off0]) : z; fma8(a2, v0, q20); }
        }
    }

    if (valid) {
        const float4* b4 = (const float4*)bias;
        float4 bb0 = b4[hl * 2], bb1 = b4[hl * 2 + 1];
        a0[0] += bb0.x; a0[1] += bb0.y; a0[2] += bb0.z; a0[3] += bb0.w;
        a0[4] += bb1.x; a0[5] += bb1.y; a0[6] += bb1.z; a0[7] += bb1.w;
        int o = row * 16 + hl;
        fout[o] = pack8(a0);
        if (M > 1) o1[o] = pack8(a1);
        if (M > 2) o2[o] = pack8(a2);
    }
}

// ---------------- mean over nodes (fp16 in) ----------------
__global__ void mean_kernel() {
    int br = blockIdx.y;
    const __half2* f2 = (const __half2*)g_feats16[br];
    int t = threadIdx.x;        // 256
    int d2 = t & 63;            // half2 column
    int grp = t >> 6;           // 0..3
    int r0 = blockIdx.x * 512 + grp * 128;
    int rend = min(r0 + 128, N_NODES);
    float2 s = make_float2(0.f, 0.f);
    for (int r = r0; r < rend; ++r) {
        float2 x = __half22float2(f2[r * 64 + d2]);
        s.x += x.x; s.y += x.y;
    }
    __shared__ float2 sm[4][64];
    sm[grp][d2] = s;
    __syncthreads();
    if (t < 64) {
        float2 tot = sm[0][t];
        tot.x += sm[1][t].x + sm[2][t].x + sm[3][t].x;
        tot.y += sm[1][t].y + sm[2][t].y + sm[3][t].y;
        atomicAdd(&g_msum[br * D + t * 2], tot.x);
        atomicAdd(&g_msum[br * D + t * 2 + 1], tot.y);
    }
}

// ---------------- tiny MLP + softmax ----------------
__global__ void mlp_kernel(const float* __restrict__ fc1w, const float* __restrict__ fc1b,
                           const float* __restrict__ fc2w, const float* __restrict__ fc2b) {
    __shared__ float m[3 * D];
    __shared__ float t1[3 * D_RED];
    int t = threadIdx.x;  // 128
    for (int i = t; i < 3 * D; i += 128) m[i] = g_msum[i] * (1.0f / N_NODES);
    __syncthreads();
    if (t < 3 * D_RED) {
        int k = t / D_RED, r = t % D_RED;
        float s = fc1b[r];
        for (int d = 0; d < D; ++d) s = fmaf(m[k * D + d], fc1w[d * D_RED + r], s);
        t1[t] = s > 0.f ? s : 0.f;
    }
    __syncthreads();
    float lg[3];
#pragma unroll
    for (int k = 0; k < 3; ++k) {
        float s = fc2b[t];
        for (int r = 0; r < D_RED; ++r) s = fmaf(t1[k * D_RED + r], fc2w[r * D + t], s);
        lg[k] = s;
    }
    float mx = fmaxf(lg[0], fmaxf(lg[1], lg[2]));
    float e0 = expf(lg[0] - mx), e1 = expf(lg[1] - mx), e2 = expf(lg[2] - mx);
    float inv = 1.f / (e0 + e1 + e2);
    g_attn[0 * D + t] = e0 * inv;
    g_attn[1 * D + t] = e1 * inv;
    g_attn[2 * D + t] = e2 * inv;
}

// ---------------- weighted combine (fp16 feats -> fp32 out) ----------------
__global__ void combine_kernel(float* __restrict__ out) {
    __shared__ float sa[3 * D];
    for (int i = threadIdx.x; i < 3 * D; i += 256) sa[i] = g_attn[i];
    __syncthreads();
    int i = blockIdx.x * 256 + threadIdx.x;   // over N_NODES*16 uint4s (exact)
    int hl = i & 15;
    uint4 q0 = ((const uint4*)g_feats16[0])[i];
    uint4 q1 = ((const uint4*)g_feats16[1])[i];
    uint4 q2 = ((const uint4*)g_feats16[2])[i];
    float f0[8], f1[8], f2[8];
    {
        float2 x;
        x = __half22float2(*(__half2*)&q0.x); f0[0] = x.x; f0[1] = x.y;
        x = __half22float2(*(__half2*)&q0.y); f0[2] = x.x; f0[3] = x.y;
        x = __half22float2(*(__half2*)&q0.z); f0[4] = x.x; f0[5] = x.y;
        x = __half22float2(*(__half2*)&q0.w); f0[6] = x.x; f0[7] = x.y;
        x = __half22float2(*(__half2*)&q1.x); f1[0] = x.x; f1[1] = x.y;
        x = __half22float2(*(__half2*)&q1.y); f1[2] = x.x; f1[3] = x.y;
        x = __half22float2(*(__half2*)&q1.z); f1[4] = x.x; f1[5] = x.y;
        x = __half22float2(*(__half2*)&q1.w); f1[6] = x.x; f1[7] = x.y;
        x = __half22float2(*(__half2*)&q2.x); f2[0] = x.x; f2[1] = x.y;
        x = __half22float2(*(__half2*)&q2.y); f2[2] = x.x; f2[3] = x.y;
        x = __half22float2(*(__half2*)&q2.z); f2[4] = x.x; f2[5] = x.y;
        x = __half22float2(*(__half2*)&q2.w); f2[6] = x.x; f2[7] = x.y;
    }
    float4 oa, ob;
    float* op = &oa.x;
#pragma unroll
    for (int k = 0; k < 8; ++k) {
        int d = hl * 8 + k;
        float r = f0[k] * sa[d] + f1[k] * sa[D + d] + f2[k] * sa[2 * D + d];
        if (k < 4) (&oa.x)[k] = r; else (&ob.x)[k - 4] = r;
    }
    (void)op;
    ((float4*)out)[i * 2] = oa;
    ((float4*)out)[i * 2 + 1] = ob;
}

// ---------------- launch ----------------
extern "C" void kernel_launch(void* const* d_in, const int* in_sizes, int n_in,
                              void* d_out, int out_size) {
    const float* features = (const float*)d_in[0];
    const int*   erow     = (const int*)d_in[1];
    const int*   ecol     = (const int*)d_in[2];
    const float* eval_    = (const float*)d_in[3];
    const float* W1 = (const float*)d_in[4];
    const float* B1 = (const float*)d_in[5];
    const float* W2 = (const float*)d_in[6];
    const float* B2 = (const float*)d_in[7];
    const float* W3 = (const float*)d_in[8];
    const float* B3 = (const float*)d_in[9];
    const float* fc1w = (const float*)d_in[10];
    const float* fc1b = (const float*)d_in[11];
    const float* fc2w = (const float*)d_in[12];
    const float* fc2b = (const float*)d_in[13];
    float* out = (float*)d_out;

    zero_kernel<<<196, 256>>>();
    count_kernel<<<(N_EDGES / 4 + 255) / 256, 256>>>(erow);
    scan_kernel<<<1, 1024>>>();
    fill_kernel<<<(N_EDGES / 4 + 255) / 256, 256>>>(erow, ecol, eval_);

    cvt_x16_kernel<<<(N_PAD * 16 + 255) / 256, 256>>>(features);
    dim3 gg(N_PAD / 64, 3);
    gemm_tanh_wmma<<<gg, 256>>>(W1, W2, W3);

    const int hop_grid = (N_NODES + 15) / 16;
    hop_kernel<3><<<hop_grid, 256>>>(B1);
    hop_kernel<2><<<hop_grid, 256>>>(B2);
    hop_kernel<1><<<hop_grid, 256>>>(B3);

    dim3 mg((N_NODES + 511) / 512, 3);
    mean_kernel<<<mg, 256>>>();
    mlp_kernel<<<1, 128>>>(fc1w, fc1b, fc2w, fc2b);
    combine_kernel<<<(N_NODES * 16) / 256, 256>>>(out);
}

// round 4
// speedup vs baseline: 1.4888x; 1.1382x over previous
#include <cuda_runtime.h>
#include <cuda_fp16.h>
#include <mma.h>
#include <math.h>

using namespace nvcuda;

#define N_NODES 50000
#define N_PAD   50048
#define N_EDGES 800000
#define D 128
#define D_RED 32

// ---------------- scratch ----------------
__device__ __half g_x16[N_PAD * D];
__device__ __half g_h[3][N_PAD * D];
__device__ __half g_bufA[N_NODES * D];
__device__ __half g_bufB[N_NODES * D];
__device__ int    g_counts[N_NODES];
__device__ int    g_rowptr[N_NODES + 1];
__device__ int    g_cursor[N_NODES];
__device__ uint2  g_epack[N_EDGES];
__device__ float  g_r1[N_NODES];
__device__ float  g_r2[N_NODES];
__device__ float  g_r3[N_NODES];
__device__ float  g_dot[3 * D];
__device__ float  g_attn[3 * D];
__device__ float  g_cb[D];

// ---------------- zero ----------------
__global__ void zero_kernel() {
    int i = blockIdx.x * blockDim.x + threadIdx.x;
    if (i < N_NODES) {
        g_counts[i] = 0;
        g_r1[i] = 0.f; g_r2[i] = 0.f; g_r3[i] = 0.f;
    }
    if (i < 3 * D) g_dot[i] = 0.f;
}

// ---------------- count + r1 = A^T 1 ----------------
__global__ void count_r1_kernel(const int* __restrict__ erow, const int* __restrict__ ecol,
                                const float* __restrict__ eval_) {
    int i = blockIdx.x * blockDim.x + threadIdx.x;
    if (i < N_EDGES / 4) {
        int4 r = ((const int4*)erow)[i];
        int4 c = ((const int4*)ecol)[i];
        float4 v = ((const float4*)eval_)[i];
        atomicAdd(&g_counts[r.x], 1);
        atomicAdd(&g_counts[r.y], 1);
        atomicAdd(&g_counts[r.z], 1);
        atomicAdd(&g_counts[r.w], 1);
        atomicAdd(&g_r1[c.x], v.x);
        atomicAdd(&g_r1[c.y], v.y);
        atomicAdd(&g_r1[c.z], v.z);
        atomicAdd(&g_r1[c.w], v.w);
    }
}

// ---------------- scan ----------------
__global__ void scan_kernel() {
    const int PER = 49;
    int t = threadIdx.x;
    int base = t * PER;
    int sum = 0;
    for (int i = 0; i < PER; ++i) {
        int idx = base + i;
        if (idx < N_NODES) sum += g_counts[idx];
    }
    int lane = t & 31, wid = t >> 5;
    int x = sum;
#pragma unroll
    for (int o = 1; o < 32; o <<= 1) {
        int y = __shfl_up_sync(0xffffffffu, x, o);
        if (lane >= o) x += y;
    }
    __shared__ int wsum[32];
    if (lane == 31) wsum[wid] = x;
    __syncthreads();
    if (wid == 0) {
        int w = wsum[lane];
#pragma unroll
        for (int o = 1; o < 32; o <<= 1) {
            int y = __shfl_up_sync(0xffffffffu, w, o);
            if (lane >= o) w += y;
        }
        wsum[lane] = w;
    }
    __syncthreads();
    int run = x - sum + (wid > 0 ? wsum[wid - 1] : 0);
    for (int i = 0; i < PER; ++i) {
        int idx = base + i;
        if (idx < N_NODES) {
            g_rowptr[idx] = run;
            g_cursor[idx] = run;
            run += g_counts[idx];
        }
    }
    if (t == 1023) g_rowptr[N_NODES] = run;
}

// ---------------- fill + r2 = A^T r1 ----------------
__global__ void fill_r2_kernel(const int* __restrict__ erow, const int* __restrict__ ecol,
                               const float* __restrict__ eval_) {
    int i = blockIdx.x * blockDim.x + threadIdx.x;
    if (i < N_EDGES / 4) {
        int4 r = ((const int4*)erow)[i];
        int4 c = ((const int4*)ecol)[i];
        float4 v = ((const float4*)eval_)[i];
        int p0 = atomicAdd(&g_cursor[r.x], 1);
        int p1 = atomicAdd(&g_cursor[r.y], 1);
        int p2 = atomicAdd(&g_cursor[r.z], 1);
        int p3 = atomicAdd(&g_cursor[r.w], 1);
        g_epack[p0] = make_uint2((unsigned)c.x, __float_as_uint(v.x));
        g_epack[p1] = make_uint2((unsigned)c.y, __float_as_uint(v.y));
        g_epack[p2] = make_uint2((unsigned)c.z, __float_as_uint(v.z));
        g_epack[p3] = make_uint2((unsigned)c.w, __float_as_uint(v.w));
        atomicAdd(&g_r2[c.x], v.x * __ldg(&g_r1[r.x]));
        atomicAdd(&g_r2[c.y], v.y * __ldg(&g_r1[r.y]));
        atomicAdd(&g_r2[c.z], v.z * __ldg(&g_r1[r.z]));
        atomicAdd(&g_r2[c.w], v.w * __ldg(&g_r1[r.w]));
    }
}

// ---------------- r3 = A^T r2 ----------------
__global__ void r3_kernel(const int* __restrict__ erow, const int* __restrict__ ecol,
                          const float* __restrict__ eval_) {
    int i = blockIdx.x * blockDim.x + threadIdx.x;
    if (i < N_EDGES / 4) {
        int4 r = ((const int4*)erow)[i];
        int4 c = ((const int4*)ecol)[i];
        float4 v = ((const float4*)eval_)[i];
        atomicAdd(&g_r3[c.x], v.x * __ldg(&g_r2[r.x]));
        atomicAdd(&g_r3[c.y], v.y * __ldg(&g_r2[r.y]));
        atomicAdd(&g_r3[c.z], v.z * __ldg(&g_r2[r.z]));
        atomicAdd(&g_r3[c.w], v.w * __ldg(&g_r2[r.w]));
    }
}

// ---------------- X -> fp16 ----------------
__global__ void cvt_x16_kernel(const float* __restrict__ X) {
    int i = blockIdx.x * blockDim.x + threadIdx.x;
    if (i >= N_PAD * 16) return;
    int r = i >> 4;
    uint4 o = make_uint4(0, 0, 0, 0);
    if (r < N_NODES) {
        const float4* x4 = (const float4*)X;
        float4 f0 = x4[i * 2], f1 = x4[i * 2 + 1];
        __half2 h0 = __floats2half2_rn(f0.x, f0.y);
        __half2 h1 = __floats2half2_rn(f0.z, f0.w);
        __half2 h2 = __floats2half2_rn(f1.x, f1.y);
        __half2 h3 = __floats2half2_rn(f1.z, f1.w);
        o.x = *(unsigned*)&h0; o.y = *(unsigned*)&h1;
        o.z = *(unsigned*)&h2; o.w = *(unsigned*)&h3;
    }
    ((uint4*)g_x16)[i] = o;
}

// ---------------- tanh(X @ Wk) ----------------
__global__ __launch_bounds__(256) void gemm_tanh_wmma(const float* __restrict__ W1,
                                                      const float* __restrict__ W2,
                                                      const float* __restrict__ W3) {
    __shared__ __half As[64 * D];
    __shared__ __half Bs[D * D];
    int k = blockIdx.y;
    const float* Wg = (k == 0) ? W1 : (k == 1) ? W2 : W3;
    __half* out = g_h[k];
    int tid = threadIdx.x;
    int row0 = blockIdx.x * 64;

    for (int i = tid; i < D * D; i += 256) Bs[i] = __float2half(Wg[i]);
    {
        const uint4* src = (const uint4*)(g_x16 + row0 * D);
        uint4* dst = (uint4*)As;
        for (int i = tid; i < 64 * 16; i += 256) dst[i] = src[i];
    }
    __syncthreads();

    int warp = tid >> 5;
    int wr = warp >> 1;
    int wc0 = (warp & 1) * 4;

    wmma::fragment<wmma::accumulator, 16, 16, 16, float> acc[4];
#pragma unroll
    for (int c = 0; c < 4; ++c) wmma::fill_fragment(acc[c], 0.f);

#pragma unroll
    for (int k16 = 0; k16 < 8; ++k16) {
        wmma::fragment<wmma::matrix_a, 16, 16, 16, __half, wmma::row_major> a;
        wmma::load_matrix_sync(a, As + wr * 16 * D + k16 * 16, D);
#pragma unroll
        for (int c = 0; c < 4; ++c) {
            wmma::fragment<wmma::matrix_b, 16, 16, 16, __half, wmma::row_major> b;
            wmma::load_matrix_sync(b, Bs + k16 * 16 * D + (wc0 + c) * 16, D);
            wmma::mma_sync(acc[c], a, b, acc[c]);
        }
    }
#pragma unroll
    for (int c = 0; c < 4; ++c) {
        wmma::fragment<wmma::accumulator, 16, 16, 16, __half> hacc;
#pragma unroll
        for (int i = 0; i < hacc.num_elements; ++i)
            hacc.x[i] = __float2half(tanhf(acc[c].x[i]));
        wmma::store_matrix_sync(out + (row0 + wr * 16) * D + (wc0 + c) * 16, hacc, D,
                                wmma::mem_row_major);
    }
}

// ---------------- dot[k][d] = sum_n r_k[n] * h_k[n,d] ----------------
__global__ void dot_kernel() {
    int br = blockIdx.y;
    const float* rk = (br == 0) ? g_r1 : (br == 1) ? g_r2 : g_r3;
    const __half2* f2 = (const __half2*)g_h[br];
    int t = threadIdx.x;        // 256
    int d2 = t & 63;
    int grp = t >> 6;
    int r0 = blockIdx.x * 512 + grp * 128;
    int rend = min(r0 + 128, N_NODES);
    float2 s = make_float2(0.f, 0.f);
    for (int r = r0; r < rend; ++r) {
        float w = __ldg(&rk[r]);
        float2 x = __half22float2(f2[r * 64 + d2]);
        s.x += w * x.x; s.y += w * x.y;
    }
    __shared__ float2 sm[4][64];
    sm[grp][d2] = s;
    __syncthreads();
    if (t < 64) {
        float2 tot = sm[0][t];
        tot.x += sm[1][t].x + sm[2][t].x + sm[3][t].x;
        tot.y += sm[1][t].y + sm[2][t].y + sm[3][t].y;
        atomicAdd(&g_dot[br * D + t * 2], tot.x);
        atomicAdd(&g_dot[br * D + t * 2 + 1], tot.y);
    }
}

// ---------------- MLP + softmax + combined bias ----------------
__global__ void mlp_kernel(const float* __restrict__ fc1w, const float* __restrict__ fc1b,
                           const float* __restrict__ fc2w, const float* __restrict__ fc2b,
                           const float* __restrict__ B1, const float* __restrict__ B2,
                           const float* __restrict__ B3) {
    __shared__ float m[3 * D];
    __shared__ float t1[3 * D_RED];
    int t = threadIdx.x;  // 128
    for (int i = t; i < 3 * D; i += 128) {
        int k = i >> 7, d = i & 127;
        const float* Bk = (k == 0) ? B1 : (k == 1) ? B2 : B3;
        m[i] = g_dot[i] * (1.0f / N_NODES) + Bk[d];
    }
    __syncthreads();
    if (t < 3 * D_RED) {
        int k = t / D_RED, r = t % D_RED;
        float s = fc1b[r];
        for (int d = 0; d < D; ++d) s = fmaf(m[k * D + d], fc1w[d * D_RED + r], s);
        t1[t] = s > 0.f ? s : 0.f;
    }
    __syncthreads();
    float lg[3];
#pragma unroll
    for (int k = 0; k < 3; ++k) {
        float s = fc2b[t];
        for (int r = 0; r < D_RED; ++r) s = fmaf(t1[k * D_RED + r], fc2w[r * D + t], s);
        lg[k] = s;
    }
    float mx = fmaxf(lg[0], fmaxf(lg[1], lg[2]));
    float e0 = expf(lg[0] - mx), e1 = expf(lg[1] - mx), e2 = expf(lg[2] - mx);
    float inv = 1.f / (e0 + e1 + e2);
    float a0 = e0 * inv, a1 = e1 * inv, a2 = e2 * inv;
    g_attn[0 * D + t] = a0;
    g_attn[1 * D + t] = a1;
    g_attn[2 * D + t] = a2;
    g_cb[t] = a0 * B1[t] + a1 * B2[t] + a2 * B3[t];
}

// ---------------- u = a3 (.) h3 ----------------
__global__ void scale_kernel() {
    int i = blockIdx.x * 256 + threadIdx.x;  // N_NODES*16 uint4 exact
    int hl = i & 15;
    const float4* a4 = (const float4*)(g_attn + 2 * D);
    float4 s0 = a4[hl * 2], s1 = a4[hl * 2 + 1];
    uint4 q = ((const uint4*)g_h[2])[i];
    float2 f0 = __half22float2(*(__half2*)&q.x);
    float2 f1 = __half22float2(*(__half2*)&q.y);
    float2 f2 = __half22float2(*(__half2*)&q.z);
    float2 f3 = __half22float2(*(__half2*)&q.w);
    __half2 h0 = __floats2half2_rn(f0.x * s0.x, f0.y * s0.y);
    __half2 h1 = __floats2half2_rn(f1.x * s0.z, f1.y * s0.w);
    __half2 h2 = __floats2half2_rn(f2.x * s1.x, f2.y * s1.y);
    __half2 h3 = __floats2half2_rn(f3.x * s1.z, f3.y * s1.w);
    uint4 o;
    o.x = *(unsigned*)&h0; o.y = *(unsigned*)&h1;
    o.z = *(unsigned*)&h2; o.w = *(unsigned*)&h3;
    ((uint4*)g_bufA)[i] = o;
}

// ---------------- hop helpers ----------------
__device__ __forceinline__ void fma8(float* a, float v, uint4 q) {
    float2 f0 = __half22float2(*reinterpret_cast<const __half2*>(&q.x));
    float2 f1 = __half22float2(*reinterpret_cast<const __half2*>(&q.y));
    float2 f2 = __half22float2(*reinterpret_cast<const __half2*>(&q.z));
    float2 f3 = __half22float2(*reinterpret_cast<const __half2*>(&q.w));
    a[0] = fmaf(v, f0.x, a[0]); a[1] = fmaf(v, f0.y, a[1]);
    a[2] = fmaf(v, f1.x, a[2]); a[3] = fmaf(v, f1.y, a[3]);
    a[4] = fmaf(v, f2.x, a[4]); a[5] = fmaf(v, f2.y, a[5]);
    a[6] = fmaf(v, f3.x, a[6]); a[7] = fmaf(v, f3.y, a[7]);
}

__device__ __forceinline__ uint4 pack8(const float* a) {
    __half2 h0 = __floats2half2_rn(a[0], a[1]);
    __half2 h1 = __floats2half2_rn(a[2], a[3]);
    __half2 h2 = __floats2half2_rn(a[4], a[5]);
    __half2 h3 = __floats2half2_rn(a[6], a[7]);
    uint4 r;
    r.x = *(unsigned*)&h0; r.y = *(unsigned*)&h1;
    r.z = *(unsigned*)&h2; r.w = *(unsigned*)&h3;
    return r;
}

// ---------------- Horner hop: dst = A src (+ a (.) h_add | + cb -> out) ----------------
template <int HOP>
__global__ __launch_bounds__(256) void hop_kernel(float* __restrict__ out) {
    const uint4* src = (HOP == 2) ? (const uint4*)g_bufB : (const uint4*)g_bufA;
    uint4* dst = (HOP == 1) ? (uint4*)g_bufB : (uint4*)g_bufA;
    const uint4* add = (HOP == 1) ? (const uint4*)g_h[1] : (const uint4*)g_h[0];
    const int acol = (HOP == 1) ? D : 0;

    int lane = threadIdx.x & 31;
    int warp = threadIdx.x >> 5;
    int hl = lane & 15;
    int halfsel = lane & 16;
    int row = blockIdx.x * 16 + warp * 2 + (lane >> 4);
    bool valid = row < N_NODES;
    int s = valid ? g_rowptr[row] : 0;
    int e = valid ? g_rowptr[row + 1] : 0;
    int nb = (e - s + 15) >> 4;
    int nbo = __shfl_xor_sync(0xffffffffu, nb, 16);
    int nbmax = max(nb, nbo);

    float a[8];
#pragma unroll
    for (int i = 0; i < 8; ++i) a[i] = 0.f;
    const uint4 z = make_uint4(0, 0, 0, 0);

    for (int it = 0; it < nbmax; ++it) {
        int b = s + it * 16;
        int idx = b + hl;
        int c = 0;
        float v = 0.f;
        if (idx < e) {
            uint2 p = __ldg(&g_epack[idx]);
            c = (int)p.x;
            v = __uint_as_float(p.y);
        }
        int cnt = min(16, max(0, e - b));
        int cnto = __shfl_xor_sync(0xffffffffu, cnt, 16);
        int cmax = max(cnt, cnto);
        int j = 0;
        for (; j + 4 <= cmax; j += 4) {
            int c0 = __shfl_sync(0xffffffffu, c, halfsel | j);
            float v0 = __shfl_sync(0xffffffffu, v, halfsel | j);
            int c1 = __shfl_sync(0xffffffffu, c, halfsel | (j + 1));
            float v1 = __shfl_sync(0xffffffffu, v, halfsel | (j + 1));
            int c2 = __shfl_sync(0xffffffffu, c, halfsel | (j + 2));
            float v2 = __shfl_sync(0xffffffffu, v, halfsel | (j + 2));
            int c3 = __shfl_sync(0xffffffffu, c, halfsel | (j + 3));
            float v3 = __shfl_sync(0xffffffffu, v, halfsel | (j + 3));
            bool d0 = j < cnt, d1 = j + 1 < cnt, d2 = j + 2 < cnt, d3 = j + 3 < cnt;
            uint4 q0 = d0 ? __ldg(&src[c0 * 16 + hl]) : z;
            uint4 q1 = d1 ? __ldg(&src[c1 * 16 + hl]) : z;
            uint4 q2 = d2 ? __ldg(&src[c2 * 16 + hl]) : z;
            uint4 q3 = d3 ? __ldg(&src[c3 * 16 + hl]) : z;
            fma8(a, v0, q0); fma8(a, v1, q1); fma8(a, v2, q2); fma8(a, v3, q3);
        }
        for (; j < cmax; ++j) {
            int c0 = __shfl_sync(0xffffffffu, c, halfsel | j);
            float v0 = __shfl_sync(0xffffffffu, v, halfsel | j);
            bool d0 = j < cnt;
            uint4 q0 = d0 ? __ldg(&src[c0 * 16 + hl]) : z;
            fma8(a, v0, q0);
        }
    }

    if (valid) {
        int o = row * 16 + hl;
        if (HOP < 3) {
            const float4* a4 = (const float4*)(g_attn + acol);
            float4 s0 = a4[hl * 2], s1 = a4[hl * 2 + 1];
            uint4 q = __ldg(&add[o]);
            float2 f0 = __half22float2(*(__half2*)&q.x);
            float2 f1 = __half22float2(*(__half2*)&q.y);
            float2 f2 = __half22float2(*(__half2*)&q.z);
            float2 f3 = __half22float2(*(__half2*)&q.w);
            a[0] = fmaf(s0.x, f0.x, a[0]); a[1] = fmaf(s0.y, f0.y, a[1]);
            a[2] = fmaf(s0.z, f1.x, a[2]); a[3] = fmaf(s0.w, f1.y, a[3]);
            a[4] = fmaf(s1.x, f2.x, a[4]); a[5] = fmaf(s1.y, f2.y, a[5]);
            a[6] = fmaf(s1.z, f3.x, a[6]); a[7] = fmaf(s1.w, f3.y, a[7]);
            dst[o] = pack8(a);
        } else {
            const float4* cb4 = (const float4*)g_cb;
            float4 c0 = cb4[hl * 2], c1 = cb4[hl * 2 + 1];
            float4 oa = make_float4(a[0] + c0.x, a[1] + c0.y, a[2] + c0.z, a[3] + c0.w);
            float4 ob = make_float4(a[4] + c1.x, a[5] + c1.y, a[6] + c1.z, a[7] + c1.w);
            ((float4*)out)[row * 32 + hl * 2] = oa;
            ((float4*)out)[row * 32 + hl * 2 + 1] = ob;
        }
    }
}

// ---------------- launch ----------------
extern "C" void kernel_launch(void* const* d_in, const int* in_sizes, int n_in,
                              void* d_out, int out_size) {
    const float* features = (const float*)d_in[0];
    const int*   erow     = (const int*)d_in[1];
    const int*   ecol     = (const int*)d_in[2];
    const float* eval_    = (const float*)d_in[3];
    const float* W1 = (const float*)d_in[4];
    const float* B1 = (const float*)d_in[5];
    const float* W2 = (const float*)d_in[6];
    const float* B2 = (const float*)d_in[7];
    const float* W3 = (const float*)d_in[8];
    const float* B3 = (const float*)d_in[9];
    const float* fc1w = (const float*)d_in[10];
    const float* fc1b = (const float*)d_in[11];
    const float* fc2w = (const float*)d_in[12];
    const float* fc2b = (const float*)d_in[13];
    float* out = (float*)d_out;

    const int eg = (N_EDGES / 4 + 255) / 256;

    zero_kernel<<<196, 256>>>();
    count_r1_kernel<<<eg, 256>>>(erow, ecol, eval_);
    scan_kernel<<<1, 1024>>>();
    fill_r2_kernel<<<eg, 256>>>(erow, ecol, eval_);
    r3_kernel<<<eg, 256>>>(erow, ecol, eval_);

    cvt_x16_kernel<<<(N_PAD * 16 + 255) / 256, 256>>>(features);
    dim3 gg(N_PAD / 64, 3);
    gemm_tanh_wmma<<<gg, 256>>>(W1, W2, W3);

    dim3 dg((N_NODES + 511) / 512, 3);
    dot_kernel<<<dg, 256>>>();
    mlp_kernel<<<1, 128>>>(fc1w, fc1b, fc2w, fc2b, B1, B2, B3);

    scale_kernel<<<(N_NODES * 16) / 256, 256>>>();
    const int hop_grid = (N_NODES + 15) / 16;
    hop_kernel<1><<<hop_grid, 256>>>(nullptr);
    hop_kernel<2><<<hop_grid, 256>>>(nullptr);
    hop_kernel<3><<<hop_grid, 256>>>(out);
}

// round 5
// speedup vs baseline: 1.5847x; 1.0644x over previous
#include <cuda_runtime.h>
#include <cuda_fp16.h>
#include <mma.h>
#include <math.h>

using namespace nvcuda;

#define N_NODES 50000
#define N_PAD   50048
#define N_EDGES 800000
#define D 128
#define D_RED 32
#define EG 782          // ceil(200000/256) edge-quarter blocks
#define DOTG 98         // ceil(50000/512) dot blocks

// ---------------- scratch ----------------
__device__ __half g_x16[N_PAD * D];
__device__ __half g_w16[3][D * D];
__device__ __half g_h[3][N_PAD * D];
__device__ __half g_bufA[N_NODES * D];
__device__ __half g_bufB[N_NODES * D];
__device__ int    g_counts[N_NODES];
__device__ int    g_rowptr[N_NODES + 1];
__device__ int    g_cursor[N_NODES];
__device__ uint2  g_epack[N_EDGES];
__device__ float  g_r1[N_NODES];
__device__ float  g_r2[N_NODES];
__device__ float  g_r3[N_NODES];
__device__ float  g_dot[3 * D];
__device__ float  g_attn[3 * D];
__device__ float  g_cb[D];

// ================= K1: zero + W->fp16 + X->fp16 =================
// blocks [0,196): zero   [196,244): W cvt   [244,3372): X cvt
__global__ __launch_bounds__(256) void k1_kernel(const float* __restrict__ X,
                                                 const float* __restrict__ W1,
                                                 const float* __restrict__ W2,
                                                 const float* __restrict__ W3) {
    int bx = blockIdx.x, tid = threadIdx.x;
    if (bx < 196) {
        int i = bx * 256 + tid;
        if (i < N_NODES) {
            g_counts[i] = 0;
            g_r1[i] = 0.f; g_r2[i] = 0.f; g_r3[i] = 0.f;
        }
        if (i < 3 * D) g_dot[i] = 0.f;
    } else if (bx < 244) {
        int idx = (bx - 196) * 256 + tid;       // 12288 total, 4 floats each
        int k = idx / 4096, o4 = idx % 4096;
        const float4* Wk4 = (const float4*)(k == 0 ? W1 : k == 1 ? W2 : W3);
        float4 w = Wk4[o4];
        __half2 h0 = __floats2half2_rn(w.x, w.y);
        __half2 h1 = __floats2half2_rn(w.z, w.w);
        ((uint2*)g_w16[k])[o4] = make_uint2(*(unsigned*)&h0, *(unsigned*)&h1);
    } else {
        int i = (bx - 244) * 256 + tid;         // over N_PAD*16 uint4
        if (i >= N_PAD * 16) return;
        int r = i >> 4;
        uint4 o = make_uint4(0, 0, 0, 0);
        if (r < N_NODES) {
            const float4* x4 = (const float4*)X;
            float4 f0 = x4[i * 2], f1 = x4[i * 2 + 1];
            __half2 h0 = __floats2half2_rn(f0.x, f0.y);
            __half2 h1 = __floats2half2_rn(f0.z, f0.w);
            __half2 h2 = __floats2half2_rn(f1.x, f1.y);
            __half2 h3 = __floats2half2_rn(f1.z, f1.w);
            o.x = *(unsigned*)&h0; o.y = *(unsigned*)&h1;
            o.z = *(unsigned*)&h2; o.w = *(unsigned*)&h3;
        }
        ((uint4*)g_x16)[i] = o;
    }
}

// ================= gemm body (device) =================
__device__ __forceinline__ void gemm_body(int k, int rb) {
    __shared__ __half As[64 * D];
    __shared__ __half Bs[D * D];
    int tid = threadIdx.x;
    int row0 = rb * 64;
    __half* out = g_h[k];

    {
        const uint4* wsrc = (const uint4*)g_w16[k];
        uint4* wdst = (uint4*)Bs;
        for (int i = tid; i < D * D / 8; i += 256) wdst[i] = wsrc[i];
        const uint4* src = (const uint4*)(g_x16 + row0 * D);
        uint4* dst = (uint4*)As;
        for (int i = tid; i < 64 * 16; i += 256) dst[i] = src[i];
    }
    __syncthreads();

    int warp = tid >> 5;
    int wr = warp >> 1;
    int wc0 = (warp & 1) * 4;

    wmma::fragment<wmma::accumulator, 16, 16, 16, float> acc[4];
#pragma unroll
    for (int c = 0; c < 4; ++c) wmma::fill_fragment(acc[c], 0.f);

#pragma unroll
    for (int k16 = 0; k16 < 8; ++k16) {
        wmma::fragment<wmma::matrix_a, 16, 16, 16, __half, wmma::row_major> a;
        wmma::load_matrix_sync(a, As + wr * 16 * D + k16 * 16, D);
#pragma unroll
        for (int c = 0; c < 4; ++c) {
            wmma::fragment<wmma::matrix_b, 16, 16, 16, __half, wmma::row_major> b;
            wmma::load_matrix_sync(b, Bs + k16 * 16 * D + (wc0 + c) * 16, D);
            wmma::mma_sync(acc[c], a, b, acc[c]);
        }
    }
#pragma unroll
    for (int c = 0; c < 4; ++c) {
        wmma::fragment<wmma::accumulator, 16, 16, 16, __half> hacc;
#pragma unroll
        for (int i = 0; i < hacc.num_elements; ++i)
            hacc.x[i] = __float2half(tanhf(acc[c].x[i]));
        wmma::store_matrix_sync(out + (row0 + wr * 16) * D + (wc0 + c) * 16, hacc, D,
                                wmma::mem_row_major);
    }
}

// ================= K2: count_r1 || gemm =================
__global__ __launch_bounds__(256) void k2_kernel(const int* __restrict__ erow,
                                                 const int* __restrict__ ecol,
                                                 const float* __restrict__ eval_) {
    int bx = blockIdx.x;
    if (bx < EG) {
        int i = bx * 256 + threadIdx.x;
        if (i < N_EDGES / 4) {
            int4 r = ((const int4*)erow)[i];
            int4 c = ((const int4*)ecol)[i];
            float4 v = ((const float4*)eval_)[i];
            atomicAdd(&g_counts[r.x], 1);
            atomicAdd(&g_counts[r.y], 1);
            atomicAdd(&g_counts[r.z], 1);
            atomicAdd(&g_counts[r.w], 1);
            atomicAdd(&g_r1[c.x], v.x);
            atomicAdd(&g_r1[c.y], v.y);
            atomicAdd(&g_r1[c.z], v.z);
            atomicAdd(&g_r1[c.w], v.w);
        }
    } else {
        int gi = bx - EG;
        gemm_body(gi / 782, gi % 782);
    }
}

// ================= K3: scan =================
__global__ void scan_kernel() {
    const int PER = 49;
    int t = threadIdx.x;
    int base = t * PER;
    int sum = 0;
    for (int i = 0; i < PER; ++i) {
        int idx = base + i;
        if (idx < N_NODES) sum += g_counts[idx];
    }
    int lane = t & 31, wid = t >> 5;
    int x = sum;
#pragma unroll
    for (int o = 1; o < 32; o <<= 1) {
        int y = __shfl_up_sync(0xffffffffu, x, o);
        if (lane >= o) x += y;
    }
    __shared__ int wsum[32];
    if (lane == 31) wsum[wid] = x;
    __syncthreads();
    if (wid == 0) {
        int w = wsum[lane];
#pragma unroll
        for (int o = 1; o < 32; o <<= 1) {
            int y = __shfl_up_sync(0xffffffffu, w, o);
            if (lane >= o) w += y;
        }
        wsum[lane] = w;
    }
    __syncthreads();
    int run = x - sum + (wid > 0 ? wsum[wid - 1] : 0);
    for (int i = 0; i < PER; ++i) {
        int idx = base + i;
        if (idx < N_NODES) {
            g_rowptr[idx] = run;
            g_cursor[idx] = run;
            run += g_counts[idx];
        }
    }
    if (t == 1023) g_rowptr[N_NODES] = run;
}

// ================= dot body (device) =================
__device__ __forceinline__ void dot_body(int br, int vb) {
    const float* rk = (br == 0) ? g_r1 : (br == 1) ? g_r2 : g_r3;
    const __half2* f2 = (const __half2*)g_h[br];
    __shared__ float2 sm[4][64];
    int t = threadIdx.x;
    int d2 = t & 63, grp = t >> 6;
    int r0 = vb * 512 + grp * 128;
    int rend = min(r0 + 128, N_NODES);
    float2 s = make_float2(0.f, 0.f);
    for (int r = r0; r < rend; ++r) {
        float w = __ldg(&rk[r]);
        float2 x = __half22float2(f2[r * 64 + d2]);
        s.x += w * x.x; s.y += w * x.y;
    }
    sm[grp][d2] = s;
    __syncthreads();
    if (t < 64) {
        float2 tot = sm[0][t];
        tot.x += sm[1][t].x + sm[2][t].x + sm[3][t].x;
        tot.y += sm[1][t].y + sm[2][t].y + sm[3][t].y;
        atomicAdd(&g_dot[br * D + t * 2], tot.x);
        atomicAdd(&g_dot[br * D + t * 2 + 1], tot.y);
    }
}

// ================= K4: fill_r2 || dot1 =================
__global__ __launch_bounds__(256) void k4_kernel(const int* __restrict__ erow,
                                                 const int* __restrict__ ecol,
                                                 const float* __restrict__ eval_) {
    int bx = blockIdx.x;
    if (bx < EG) {
        int i = bx * 256 + threadIdx.x;
        if (i < N_EDGES / 4) {
            int4 r = ((const int4*)erow)[i];
            int4 c = ((const int4*)ecol)[i];
            float4 v = ((const float4*)eval_)[i];
            int p0 = atomicAdd(&g_cursor[r.x], 1);
            int p1 = atomicAdd(&g_cursor[r.y], 1);
            int p2 = atomicAdd(&g_cursor[r.z], 1);
            int p3 = atomicAdd(&g_cursor[r.w], 1);
            g_epack[p0] = make_uint2((unsigned)c.x, __float_as_uint(v.x));
            g_epack[p1] = make_uint2((unsigned)c.y, __float_as_uint(v.y));
            g_epack[p2] = make_uint2((unsigned)c.z, __float_as_uint(v.z));
            g_epack[p3] = make_uint2((unsigned)c.w, __float_as_uint(v.w));
            atomicAdd(&g_r2[c.x], v.x * __ldg(&g_r1[r.x]));
            atomicAdd(&g_r2[c.y], v.y * __ldg(&g_r1[r.y]));
            atomicAdd(&g_r2[c.z], v.z * __ldg(&g_r1[r.z]));
            atomicAdd(&g_r2[c.w], v.w * __ldg(&g_r1[r.w]));
        }
    } else {
        dot_body(0, bx - EG);
    }
}

// ================= K5: r3 || dot2 =================
__global__ __launch_bounds__(256) void k5_kernel(const int* __restrict__ erow,
                                                 const int* __restrict__ ecol,
                                                 const float* __restrict__ eval_) {
    int bx = blockIdx.x;
    if (bx < EG) {
        int i = bx * 256 + threadIdx.x;
        if (i < N_EDGES / 4) {
            int4 r = ((const int4*)erow)[i];
            int4 c = ((const int4*)ecol)[i];
            float4 v = ((const float4*)eval_)[i];
            atomicAdd(&g_r3[c.x], v.x * __ldg(&g_r2[r.x]));
            atomicAdd(&g_r3[c.y], v.y * __ldg(&g_r2[r.y]));
            atomicAdd(&g_r3[c.z], v.z * __ldg(&g_r2[r.z]));
            atomicAdd(&g_r3[c.w], v.w * __ldg(&g_r2[r.w]));
        }
    } else {
        dot_body(1, bx - EG);
    }
}

// ================= K6: dot3 =================
__global__ __launch_bounds__(256) void k6_kernel() {
    dot_body(2, blockIdx.x);
}

// ================= K7: MLP + softmax + combined bias =================
__global__ void mlp_kernel(const float* __restrict__ fc1w, const float* __restrict__ fc1b,
                           const float* __restrict__ fc2w, const float* __restrict__ fc2b,
                           const float* __restrict__ B1, const float* __restrict__ B2,
                           const float* __restrict__ B3) {
    __shared__ float m[3 * D];
    __shared__ float t1[3 * D_RED];
    int t = threadIdx.x;  // 128
    for (int i = t; i < 3 * D; i += 128) {
        int k = i >> 7, d = i & 127;
        const float* Bk = (k == 0) ? B1 : (k == 1) ? B2 : B3;
        m[i] = g_dot[i] * (1.0f / N_NODES) + Bk[d];
    }
    __syncthreads();
    if (t < 3 * D_RED) {
        int k = t / D_RED, r = t % D_RED;
        float s = fc1b[r];
        for (int d = 0; d < D; ++d) s = fmaf(m[k * D + d], fc1w[d * D_RED + r], s);
        t1[t] = s > 0.f ? s : 0.f;
    }
    __syncthreads();
    float lg[3];
#pragma unroll
    for (int k = 0; k < 3; ++k) {
        float s = fc2b[t];
        for (int r = 0; r < D_RED; ++r) s = fmaf(t1[k * D_RED + r], fc2w[r * D + t], s);
        lg[k] = s;
    }
    float mx = fmaxf(lg[0], fmaxf(lg[1], lg[2]));
    float e0 = expf(lg[0] - mx), e1 = expf(lg[1] - mx), e2 = expf(lg[2] - mx);
    float inv = 1.f / (e0 + e1 + e2);
    float a0 = e0 * inv, a1 = e1 * inv, a2 = e2 * inv;
    g_attn[0 * D + t] = a0;
    g_attn[1 * D + t] = a1;
    g_attn[2 * D + t] = a2;
    g_cb[t] = a0 * B1[t] + a1 * B2[t] + a2 * B3[t];
}

// ================= hop helpers =================
__device__ __forceinline__ void fma8(float* a, float v, uint4 q) {
    float2 f0 = __half22float2(*reinterpret_cast<const __half2*>(&q.x));
    float2 f1 = __half22float2(*reinterpret_cast<const __half2*>(&q.y));
    float2 f2 = __half22float2(*reinterpret_cast<const __half2*>(&q.z));
    float2 f3 = __half22float2(*reinterpret_cast<const __half2*>(&q.w));
    a[0] = fmaf(v, f0.x, a[0]); a[1] = fmaf(v, f0.y, a[1]);
    a[2] = fmaf(v, f1.x, a[2]); a[3] = fmaf(v, f1.y, a[3]);
    a[4] = fmaf(v, f2.x, a[4]); a[5] = fmaf(v, f2.y, a[5]);
    a[6] = fmaf(v, f3.x, a[6]); a[7] = fmaf(v, f3.y, a[7]);
}

__device__ __forceinline__ void unpack8(uint4 q, float* f) {
    float2 x;
    x = __half22float2(*(__half2*)&q.x); f[0] = x.x; f[1] = x.y;
    x = __half22float2(*(__half2*)&q.y); f[2] = x.x; f[3] = x.y;
    x = __half22float2(*(__half2*)&q.z); f[4] = x.x; f[5] = x.y;
    x = __half22float2(*(__half2*)&q.w); f[6] = x.x; f[7] = x.y;
}

__device__ __forceinline__ uint4 pack8(const float* a) {
    __half2 h0 = __floats2half2_rn(a[0], a[1]);
    __half2 h1 = __floats2half2_rn(a[2], a[3]);
    __half2 h2 = __floats2half2_rn(a[4], a[5]);
    __half2 h3 = __floats2half2_rn(a[6], a[7]);
    uint4 r;
    r.x = *(unsigned*)&h0; r.y = *(unsigned*)&h1;
    r.z = *(unsigned*)&h2; r.w = *(unsigned*)&h3;
    return r;
}

// ================= Horner hops =================
// hop1: bufB = a3 (.) (A h3) + a2 (.) h2
// hop2: bufA = A bufB + a1 (.) h1
// hop3: out  = A bufA + cb         (fp32)
template <int HOP>
__global__ __launch_bounds__(256) void hop_kernel(float* __restrict__ out) {
    const uint4* src = (HOP == 1) ? (const uint4*)g_h[2]
                     : (HOP == 2) ? (const uint4*)g_bufB
                                  : (const uint4*)g_bufA;

    int lane = threadIdx.x & 31;
    int warp = threadIdx.x >> 5;
    int hl = lane & 15;
    int halfsel = lane & 16;
    int row = blockIdx.x * 16 + warp * 2 + (lane >> 4);
    bool valid = row < N_NODES;
    int s = valid ? g_rowptr[row] : 0;
    int e = valid ? g_rowptr[row + 1] : 0;
    int nb = (e - s + 15) >> 4;
    int nbmax = max(nb, __shfl_xor_sync(0xffffffffu, nb, 16));

    float a[8];
#pragma unroll
    for (int i = 0; i < 8; ++i) a[i] = 0.f;
    const uint4 z = make_uint4(0, 0, 0, 0);

    int idx0 = s + hl;
    uint2 p = (idx0 < e) ? __ldg(&g_epack[idx0]) : make_uint2(0, 0);

    for (int it = 0; it < nbmax; ++it) {
        int b = s + it * 16;
        int c = (int)p.x;
        float v = __uint_as_float(p.y);
        int nidx = b + 16 + hl;
        uint2 pn = (nidx < e) ? __ldg(&g_epack[nidx]) : make_uint2(0, 0);
        int cnt = min(16, max(0, e - b));
        int cmax = max(cnt, __shfl_xor_sync(0xffffffffu, cnt, 16));

        {
            uint4 q[8];
#pragma unroll
            for (int k = 0; k < 8; ++k) {
                int ck = __shfl_sync(0xffffffffu, c, halfsel | k);
                q[k] = (k < cnt) ? __ldg(&src[ck * 16 + hl]) : z;
            }
#pragma unroll
            for (int k = 0; k < 8; ++k) {
                float vk = __shfl_sync(0xffffffffu, v, halfsel | k);
                fma8(a, vk, q[k]);
            }
        }
        if (cmax > 8) {
            uint4 q[8];
#pragma unroll
            for (int k = 0; k < 8; ++k) {
                int ck = __shfl_sync(0xffffffffu, c, halfsel | (8 + k));
                q[k] = (8 + k < cnt) ? __ldg(&src[ck * 16 + hl]) : z;
            }
#pragma unroll
            for (int k = 0; k < 8; ++k) {
                float vk = __shfl_sync(0xffffffffu, v, halfsel | (8 + k));
                fma8(a, vk, q[k]);
            }
        }
        p = pn;
    }

    if (valid) {
        int o = row * 16 + hl;
        if (HOP == 1) {
            const float4* a3 = (const float4*)(g_attn + 2 * D);
            const float4* a2 = (const float4*)(g_attn + 1 * D);
            float4 s30 = a3[hl * 2], s31 = a3[hl * 2 + 1];
            float4 s20 = a2[hl * 2], s21 = a2[hl * 2 + 1];
            float f[8];
            unpack8(__ldg(&((const uint4*)g_h[1])[o]), f);
            float r[8];
            r[0] = s30.x * a[0] + s20.x * f[0]; r[1] = s30.y * a[1] + s20.y * f[1];
            r[2] = s30.z * a[2] + s20.z * f[2]; r[3] = s30.w * a[3] + s20.w * f[3];
            r[4] = s31.x * a[4] + s21.x * f[4]; r[5] = s31.y * a[5] + s21.y * f[5];
            r[6] = s31.z * a[6] + s21.z * f[6]; r[7] = s31.w * a[7] + s21.w * f[7];
            ((uint4*)g_bufB)[o] = pack8(r);
        } else if (HOP == 2) {
            const float4* a1 = (const float4*)g_attn;
            float4 s10 = a1[hl * 2], s11 = a1[hl * 2 + 1];
            float f[8];
            unpack8(__ldg(&((const uint4*)g_h[0])[o]), f);
            a[0] = fmaf(s10.x, f[0], a[0]); a[1] = fmaf(s10.y, f[1], a[1]);
            a[2] = fmaf(s10.z, f[2], a[2]); a[3] = fmaf(s10.w, f[3], a[3]);
            a[4] = fmaf(s11.x, f[4], a[4]); a[5] = fmaf(s11.y, f[5], a[5]);
            a[6] = fmaf(s11.z, f[6], a[6]); a[7] = fmaf(s11.w, f[7], a[7]);
            ((uint4*)g_bufA)[o] = pack8(a);
        } else {
            const float4* cb4 = (const float4*)g_cb;
            float4 c0 = cb4[hl * 2], c1 = cb4[hl * 2 + 1];
            float4 oa = make_float4(a[0] + c0.x, a[1] + c0.y, a[2] + c0.z, a[3] + c0.w);
            float4 ob = make_float4(a[4] + c1.x, a[5] + c1.y, a[6] + c1.z, a[7] + c1.w);
            ((float4*)out)[row * 32 + hl * 2] = oa;
            ((float4*)out)[row * 32 + hl * 2 + 1] = ob;
        }
    }
}

// ================= launch =================
extern "C" void kernel_launch(void* const* d_in, const int* in_sizes, int n_in,
                              void* d_out, int out_size) {
    const float* features = (const float*)d_in[0];
    const int*   erow     = (const int*)d_in[1];
    const int*   ecol     = (const int*)d_in[2];
    const float* eval_    = (const float*)d_in[3];
    const float* W1 = (const float*)d_in[4];
    const float* B1 = (const float*)d_in[5];
    const float* W2 = (const float*)d_in[6];
    const float* B2 = (const float*)d_in[7];
    const float* W3 = (const float*)d_in[8];
    const float* B3 = (const float*)d_in[9];
    const float* fc1w = (const float*)d_in[10];
    const float* fc1b = (const float*)d_in[11];
    const float* fc2w = (const float*)d_in[12];
    const float* fc2b = (const float*)d_in[13];
    float* out = (float*)d_out;

    k1_kernel<<<196 + 48 + 3128, 256>>>(features, W1, W2, W3);
    k2_kernel<<<EG + 3 * 782, 256>>>(erow, ecol, eval_);
    scan_kernel<<<1, 1024>>>();
    k4_kernel<<<EG + DOTG, 256>>>(erow, ecol, eval_);
    k5_kernel<<<EG + DOTG, 256>>>(erow, ecol, eval_);
    k6_kernel<<<DOTG, 256>>>();
    mlp_kernel<<<1, 128>>>(fc1w, fc1b, fc2w, fc2b, B1, B2, B3);

    const int hop_grid = (N_NODES + 15) / 16;
    hop_kernel<1><<<hop_grid, 256>>>(nullptr);
    hop_kernel<2><<<hop_grid, 256>>>(nullptr);
    hop_kernel<3><<<hop_grid, 256>>>(out);
}